// round 10
// baseline (speedup 1.0000x reference)
#include <cuda_runtime.h>
#include <cuda_fp16.h>
#include <mma.h>
#include <cstddef>
#include <cstdint>

using namespace nvcuda;

// Problem dims (fixed by the dataset)
#define B_   256
#define L_   64
#define DI_  2048
#define T_   32
#define DT_  512
#define U_   512
#define A_   512
#define U3_  1536
#define HN_  2048   // combined h-GEMM output: hproj(512) | mi(1536)
#define NF_  2048   // fused img GEMM width: imgproj(512) | imgk(1536)

// ---------------- device scratch (static, allocation-free) ----------------
__device__ __half g_img16  [(size_t)B_*L_*DI_];     // fp16 img [M,K] row-major
__device__ __half g_text16 [(size_t)B_*T_*DT_];
__device__ __half g_Wbig   [(size_t)DI_*NF_];       // [wimg | wctx]  [K=2048, N=2048] row-major
__device__ __half g_Wtext  [(size_t)DT_*U3_];       // kernel[:512]   [K=512,  N=1536] row-major
__device__ float  g_bias2048[NF_];                  // [att_img_bias | 0]
__device__ __half g_Wh16   [U_*HN_];                // [att_hidden | recurrent] row-major
__device__ float  g_hbias  [HN_];
__device__ __half g_imgpk  [(size_t)B_*L_*NF_];     // fused: imgproj | imgk
__device__ float  g_mxtext [(size_t)B_*T_*U3_];     // text @ kernel[:512] + bias
__device__ float  g_hmi    [B_*HN_];                // per-step h-GEMM out
__device__ float  g_h      [B_*U_];
__device__ __half g_h16    [B_*U_];
__device__ unsigned g_barcnt;

// ---------------- small helpers ----------------
__device__ __forceinline__ float tanh_fast(float x) {
    float y; asm("tanh.approx.f32 %0, %1;" : "=f"(y) : "f"(x)); return y;
}
__device__ __forceinline__ void cp_async16(void* sm, const void* gm) {
    unsigned s = (unsigned)__cvta_generic_to_shared(sm);
    asm volatile("cp.async.cg.shared.global [%0], [%1], 16;\n" :: "r"(s), "l"(gm));
}
__device__ __forceinline__ void cp_commit() { asm volatile("cp.async.commit_group;\n"); }
__device__ __forceinline__ void cp_wait0()  { asm volatile("cp.async.wait_group 0;\n"); }

// software grid barrier (all CTAs resident by construction)
__device__ __forceinline__ void grid_sync(unsigned target) {
    __syncthreads();
    if (threadIdx.x == 0) {
        asm volatile("fence.acq_rel.gpu;" ::: "memory");
        asm volatile("red.relaxed.gpu.add.u32 [%0], 1;" :: "l"(&g_barcnt) : "memory");
        unsigned v;
        do {
            asm volatile("ld.acquire.gpu.u32 %0, [%1];" : "=r"(v) : "l"(&g_barcnt) : "memory");
            if (v < target) __nanosleep(32);
        } while (v < target);
    }
    __syncthreads();
}

// ---------------- setup kernels (exactly 5 launches before the big GEMM) ---
// launch 0/1: vectorized fp32 -> fp16
__global__ void cvt_f32_f16_v8(const float* __restrict__ s, __half* __restrict__ d, size_t n8) {
    size_t i = (size_t)blockIdx.x * blockDim.x + threadIdx.x;
    if (i >= n8) return;
    const float4* s4 = reinterpret_cast<const float4*>(s) + i * 2;
    float4 a = s4[0], b = s4[1];
    __half2 h[4];
    h[0] = __floats2half2_rn(a.x, a.y);
    h[1] = __floats2half2_rn(a.z, a.w);
    h[2] = __floats2half2_rn(b.x, b.y);
    h[3] = __floats2half2_rn(b.z, b.w);
    reinterpret_cast<uint4*>(d)[i] = *reinterpret_cast<uint4*>(h);
}

// launch 2: copy+cvt the three K-major weight slabs (NO transpose — the
// sources are already [K,N] row-major, exactly what gemm_pipe's B wants).
//   job 0: wimg          [2048 x 512 ] -> g_Wbig cols [0,512)    (dst_ld 2048)
//   job 1: kernel[512:]  [2048 x 1536] -> g_Wbig cols [512,2048) (dst_ld 2048)
//   job 2: kernel[:512]  [512  x 1536] -> g_Wtext                (dst_ld 1536)
// 8 halves per thread; every col offset is a multiple of 8 -> 16B aligned.
__global__ void copy_weights(const float* __restrict__ wimg, const float* __restrict__ kernel) {
    const int job = blockIdx.y;
    const float* src; __half* dst;
    int rows, cols, dst_ld, n0out;
    if (job == 0)      { src = wimg;                       rows = DI_; cols = 512;  dst = g_Wbig;  dst_ld = NF_; n0out = 0;   }
    else if (job == 1) { src = kernel + (size_t)DT_ * U3_; rows = DI_; cols = U3_;  dst = g_Wbig;  dst_ld = NF_; n0out = 512; }
    else               { src = kernel;                     rows = DT_; cols = U3_;  dst = g_Wtext; dst_ld = U3_; n0out = 0;   }
    const int cols8 = cols / 8;
    const int total = rows * cols8;
    for (int i8 = blockIdx.x * blockDim.x + threadIdx.x; i8 < total;
         i8 += gridDim.x * blockDim.x) {
        int r = i8 / cols8, c = (i8 % cols8) * 8;
        const float* sp = src + (size_t)r * cols + c;
        float4 a = reinterpret_cast<const float4*>(sp)[0];
        float4 b = reinterpret_cast<const float4*>(sp)[1];
        __half2 h[4];
        h[0] = __floats2half2_rn(a.x, a.y);
        h[1] = __floats2half2_rn(a.z, a.w);
        h[2] = __floats2half2_rn(b.x, b.y);
        h[3] = __floats2half2_rn(b.z, b.w);
        *reinterpret_cast<uint4*>(dst + (size_t)r * dst_ld + n0out + c) =
            *reinterpret_cast<uint4*>(h);
    }
}

// launch 3: Wh = [att_hidden | recurrent] fp16 row-major
__global__ void build_Wh_v8(const float* __restrict__ attk, const float* __restrict__ reck) {
    int i8 = blockIdx.x * blockDim.x + threadIdx.x;     // U_*HN_/8
    if (i8 >= U_ * HN_ / 8) return;
    int k = i8 >> 8, c = (i8 & 255) * 8;
    const float* src = (c < 512) ? (attk + (size_t)k * 512 + c)
                                 : (reck + (size_t)k * U3_ + (c - 512));
    float4 a = reinterpret_cast<const float4*>(src)[0];
    float4 b = reinterpret_cast<const float4*>(src)[1];
    __half2 h[4];
    h[0] = __floats2half2_rn(a.x, a.y);
    h[1] = __floats2half2_rn(a.z, a.w);
    h[2] = __floats2half2_rn(b.x, b.y);
    h[3] = __floats2half2_rn(b.z, b.w);
    reinterpret_cast<uint4*>(g_Wh16)[i8] = *reinterpret_cast<uint4*>(h);
}

// launch 4: biases + h init + barrier reset
__global__ void build_misc(const float* __restrict__ bimg,
                           const float* __restrict__ attb, const float* __restrict__ recb) {
    int i = blockIdx.x * blockDim.x + threadIdx.x;
    if (i == 0) g_barcnt = 0;
    if (i < NF_) g_bias2048[i] = (i < 512) ? bimg[i] : 0.f;
    if (i < HN_) g_hbias[i]    = (i < 512) ? attb[i] : recb[i - 512];
    if (i < B_ * U_) { g_h[i] = 0.f; g_h16[i] = __float2half(0.f); }
}

// ---------------- cp.async double-buffered WMMA GEMM -----------------------
// C[M,N] = A[M,K] @ B[K,N] (+bias via accumulator init), out fp32 or fp16.
// 256 threads = 8 warps; warp tile WMxWN. Dynamic smem (2 stages).
template<int BM, int BN, int BK, int WM, int WN, bool OUT_HALF>
__global__ __launch_bounds__(256)
void gemm_pipe(const __half* __restrict__ A, const __half* __restrict__ Bm,
               const float* __restrict__ bias, float* __restrict__ Cf,
               __half* __restrict__ Ch, int M, int N, int K)
{
    constexpr int WARPS_M = BM / WM, WARPS_N = BN / WN;
    static_assert(WARPS_M * WARPS_N == 8, "8 warps");
    constexpr int FM = WM / 16, FN = WN / 16;
    constexpr int ASTR = BK + 8, BSTR = BN + 8;          // half strides (16B-mult rows)
    constexpr int ABYTES = BM * ASTR * 2, BBYTES = BK * BSTR * 2;
    extern __shared__ __align__(16) char smem[];

    const int tid = threadIdx.x, lane = tid & 31, wid = tid >> 5;
    const int wm = wid / WARPS_N, wn = wid % WARPS_N;
    const int m0 = blockIdx.x * BM, n0 = blockIdx.y * BN;

    wmma::fragment<wmma::accumulator, 16, 16, 16, float> acc[FM][FN];

    // bias folded into accumulator init via 16-row broadcast tile in smem
    if (bias) {
        float* biasT = reinterpret_cast<float*>(smem);   // [16][BN]
        for (int idx = tid; idx < 16 * BN; idx += 256) biasT[idx] = bias[n0 + (idx % BN)];
        __syncthreads();
        #pragma unroll
        for (int i = 0; i < FM; i++)
            #pragma unroll
            for (int j = 0; j < FN; j++)
                wmma::load_matrix_sync(acc[i][j], biasT + wn * WN + j * 16, BN,
                                       wmma::mem_row_major);
        __syncthreads();
    } else {
        #pragma unroll
        for (int i = 0; i < FM; i++)
            #pragma unroll
            for (int j = 0; j < FN; j++) wmma::fill_fragment(acc[i][j], 0.f);
    }

    auto As = [&](int s) { return reinterpret_cast<__half*>(smem + s * ABYTES); };
    auto Bs = [&](int s) { return reinterpret_cast<__half*>(smem + 2 * ABYTES + s * BBYTES); };

    auto load_tiles = [&](int s, int k0) {
        __half* a = As(s);
        constexpr int AV = BM * BK / 8;
        #pragma unroll
        for (int v = tid; v < AV; v += 256) {
            int r = v / (BK / 8), c = (v % (BK / 8)) * 8;
            cp_async16(a + r * ASTR + c, A + (size_t)(m0 + r) * K + k0 + c);
        }
        __half* b = Bs(s);
        constexpr int BV = BK * BN / 8;
        #pragma unroll
        for (int v = tid; v < BV; v += 256) {
            int r = v / (BN / 8), c = (v % (BN / 8)) * 8;
            cp_async16(b + r * BSTR + c, Bm + (size_t)(k0 + r) * N + n0 + c);
        }
    };

    const int KT = K / BK;
    load_tiles(0, 0);
    cp_commit();

    for (int kt = 0; kt < KT; kt++) {
        const int cur = kt & 1;
        cp_wait0();
        __syncthreads();
        if (kt + 1 < KT) { load_tiles(cur ^ 1, (kt + 1) * BK); cp_commit(); }

        const __half* a = As(cur);
        const __half* b = Bs(cur);
        #pragma unroll
        for (int kk = 0; kk < BK / 16; kk++) {
            wmma::fragment<wmma::matrix_a, 16, 16, 16, __half, wmma::row_major> af[FM];
            wmma::fragment<wmma::matrix_b, 16, 16, 16, __half, wmma::row_major> bf[FN];
            #pragma unroll
            for (int i = 0; i < FM; i++)
                wmma::load_matrix_sync(af[i], a + (wm * WM + i * 16) * ASTR + kk * 16, ASTR);
            #pragma unroll
            for (int j = 0; j < FN; j++)
                wmma::load_matrix_sync(bf[j], b + (kk * 16) * BSTR + wn * WN + j * 16, BSTR);
            #pragma unroll
            for (int i = 0; i < FM; i++)
                #pragma unroll
                for (int j = 0; j < FN; j++)
                    wmma::mma_sync(acc[i][j], af[i], bf[j], acc[i][j]);
        }
        __syncthreads();
    }

    if (OUT_HALF) {
        // per-warp smem staging (aliases pipeline buffers) -> fp16 uint4 stores
        float* stageW = reinterpret_cast<float*>(smem) + wid * 16 * 20;   // [16][20]
        const int r = lane >> 1, c0 = (lane & 1) * 8;
        #pragma unroll
        for (int i = 0; i < FM; i++)
            #pragma unroll
            for (int j = 0; j < FN; j++) {
                wmma::store_matrix_sync(stageW, acc[i][j], 20, wmma::mem_row_major);
                __syncwarp();
                const float* sp = stageW + r * 20 + c0;
                __half2 h[4];
                h[0] = __floats2half2_rn(sp[0], sp[1]);
                h[1] = __floats2half2_rn(sp[2], sp[3]);
                h[2] = __floats2half2_rn(sp[4], sp[5]);
                h[3] = __floats2half2_rn(sp[6], sp[7]);
                size_t g = (size_t)(m0 + wm * WM + i * 16 + r) * N
                         + n0 + wn * WN + j * 16 + c0;
                *reinterpret_cast<uint4*>(Ch + g) = *reinterpret_cast<uint4*>(h);
                __syncwarp();
            }
    } else {
        #pragma unroll
        for (int i = 0; i < FM; i++)
            #pragma unroll
            for (int j = 0; j < FN; j++)
                wmma::store_matrix_sync(
                    Cf + (size_t)(m0 + wm * WM + i * 16) * N + n0 + wn * WN + j * 16,
                    acc[i][j], N, wmma::mem_row_major);
    }
}

// ---------------- persistent fused step loop (R6-proven, unchanged) -------
#define G_ASTR (64 + 8)
#define G_BSTR (32 + 8)
#define G_ABYTES (64 * G_ASTR * 2)
#define G_BBYTES (64 * G_BSTR * 2)

struct PersistSmem {
    float sv[A_];            // persistent: att_v kernel
    float sbias[16 * 32];    // persistent: bias broadcast tile for G
    union {
        char  gbuf[2 * (G_ABYTES + G_BBYTES)];
        struct { float hp[A_]; float sc[L_]; float att[L_]; } s;
    } u;
};

__global__ __launch_bounds__(256, 2)
void persist_loop(const float* __restrict__ v, float* __restrict__ out)
{
    __shared__ PersistSmem sm;
    const int tid = threadIdx.x, lane = tid & 31, wid = tid >> 5;
    const int cta = blockIdx.x;

    const int gm0 = (cta >> 6) * 64;
    const int gn0 = (cta & 63) * 32;
    const int wm = wid >> 1, wn = wid & 1;

    for (int j = tid; j < A_; j += 256) sm.sv[j] = v[j];
    for (int j = tid; j < 16 * 32; j += 256) sm.sbias[j] = g_hbias[gn0 + (j & 31)];
    __syncthreads();

    unsigned nbar = 0;

    for (int t = 0; t < T_; t++) {
        // Phase G: hmi = h16 @ Wh16 + hbias
        {
            wmma::fragment<wmma::accumulator, 16, 16, 16, float> acc;
            wmma::load_matrix_sync(acc, sm.sbias + wn * 16, 32, wmma::mem_row_major);

            auto As = [&](int s) { return reinterpret_cast<__half*>(sm.u.gbuf + s * (G_ABYTES + G_BBYTES)); };
            auto Bs = [&](int s) { return reinterpret_cast<__half*>(sm.u.gbuf + s * (G_ABYTES + G_BBYTES) + G_ABYTES); };
            auto load_tiles = [&](int s, int k0) {
                __half* a = As(s);
                #pragma unroll
                for (int vv = tid; vv < 64 * 64 / 8; vv += 256) {
                    int r = vv >> 3, c = (vv & 7) * 8;
                    cp_async16(a + r * G_ASTR + c, g_h16 + (size_t)(gm0 + r) * U_ + k0 + c);
                }
                __half* b = Bs(s);
                #pragma unroll
                for (int vv = tid; vv < 64 * 32 / 8; vv += 256) {
                    int r = vv >> 2, c = (vv & 3) * 8;
                    cp_async16(b + r * G_BSTR + c, g_Wh16 + (size_t)(k0 + r) * HN_ + gn0 + c);
                }
            };

            load_tiles(0, 0);
            cp_commit();
            #pragma unroll
            for (int kt = 0; kt < 8; kt++) {
                cp_wait0();
                __syncthreads();
                if (kt + 1 < 8) { load_tiles((kt + 1) & 1, (kt + 1) * 64); cp_commit(); }
                const __half* a = As(kt & 1);
                const __half* b = Bs(kt & 1);
                #pragma unroll
                for (int kk = 0; kk < 4; kk++) {
                    wmma::fragment<wmma::matrix_a, 16, 16, 16, __half, wmma::row_major> af;
                    wmma::fragment<wmma::matrix_b, 16, 16, 16, __half, wmma::row_major> bf;
                    wmma::load_matrix_sync(af, a + (wm * 16) * G_ASTR + kk * 16, G_ASTR);
                    wmma::load_matrix_sync(bf, b + (kk * 16) * G_BSTR + wn * 16, G_BSTR);
                    wmma::mma_sync(acc, af, bf, acc);
                }
                __syncthreads();
            }
            wmma::store_matrix_sync(g_hmi + (size_t)(gm0 + wm * 16) * HN_ + gn0 + wn * 16,
                                    acc, HN_, wmma::mem_row_major);
        }
        grid_sync(++nbar * 256u);

        // Phase S: attention + softmax + ctx + gates
        {
            const int b = cta;
            const float* hmi = g_hmi + b * HN_;
            for (int j = tid; j < A_; j += 256) sm.u.s.hp[j] = __ldcg(&hmi[j]);
            __syncthreads();

            const __half2* base2 = reinterpret_cast<const __half2*>(g_imgpk + (size_t)b * L_ * NF_);
            for (int l = wid; l < L_; l += 8) {
                const __half2* ip = base2 + (size_t)l * (NF_ / 2);
                float s = 0.f;
                #pragma unroll 4
                for (int a2 = lane; a2 < A_ / 2; a2 += 32) {
                    float2 f = __half22float2(ip[a2]);
                    int a = a2 * 2;
                    s += tanh_fast(f.x + sm.u.s.hp[a])     * sm.sv[a];
                    s += tanh_fast(f.y + sm.u.s.hp[a + 1]) * sm.sv[a + 1];
                }
                #pragma unroll
                for (int o = 16; o; o >>= 1) s += __shfl_xor_sync(0xffffffffu, s, o);
                if (!lane) sm.u.s.sc[l] = s;
            }
            __syncthreads();

            if (tid < 32) {
                float v1 = sm.u.s.sc[tid], v2 = sm.u.s.sc[tid + 32];
                float m = fmaxf(v1, v2);
                #pragma unroll
                for (int o = 16; o; o >>= 1) m = fmaxf(m, __shfl_xor_sync(0xffffffffu, m, o));
                float e1 = expf(v1 - m), e2 = expf(v2 - m);
                float ssum = e1 + e2;
                #pragma unroll
                for (int o = 16; o; o >>= 1) ssum += __shfl_xor_sync(0xffffffffu, ssum, o);
                float inv = 1.f / ssum;
                sm.u.s.att[tid] = e1 * inv;
                sm.u.s.att[tid + 32] = e2 * inv;
            }
            __syncthreads();

            float acc6[6] = {0.f, 0.f, 0.f, 0.f, 0.f, 0.f};
            for (int l = 0; l < L_; l++) {
                float w = sm.u.s.att[l];
                const __half2* row = base2 + (size_t)l * (NF_ / 2) + 256;
                #pragma unroll
                for (int c = 0; c < 3; c++) {
                    float2 f = __half22float2(row[tid + c * 256]);
                    acc6[2 * c]     += w * f.x;
                    acc6[2 * c + 1] += w * f.y;
                }
            }

            const float* mxt = g_mxtext + ((size_t)b * T_ + t) * U3_;
            #pragma unroll
            for (int p = 0; p < 2; p++) {
                int u = tid * 2 + p;
                float xz = mxt[u]        + acc6[p];
                float xr = mxt[512 + u]  + acc6[2 + p];
                float xh = mxt[1024 + u] + acc6[4 + p];
                float rz = __ldcg(&hmi[512 + u]);
                float rr = __ldcg(&hmi[1024 + u]);
                float rh = __ldcg(&hmi[1536 + u]);
                float z  = 1.f / (1.f + expf(-(xz + rz)));
                float r  = 1.f / (1.f + expf(-(xr + rr)));
                float hh = tanhf(xh + r * rh);
                float ho = g_h[b * U_ + u];
                float hn = z * ho + (1.f - z) * hh;
                out[((size_t)b * T_ + t) * U_ + u] = hn;
                g_h[b * U_ + u]   = hn;
                g_h16[b * U_ + u] = __float2half(hn);
            }
        }
        if (t + 1 < T_) grid_sync(++nbar * 256u);
    }
}

// ---------------- host launcher ----------------
extern "C" void kernel_launch(void* const* d_in, const int* in_sizes, int n_in,
                              void* d_out, int out_size)
{
    const float* img    = (const float*)d_in[0];
    const float* text   = (const float*)d_in[1];
    const float* kernel = (const float*)d_in[2];
    const float* ibias  = (const float*)d_in[3];
    const float* reck   = (const float*)d_in[4];
    const float* rbias  = (const float*)d_in[5];
    const float* wimg   = (const float*)d_in[6];
    const float* bimg   = (const float*)d_in[7];
    const float* attk   = (const float*)d_in[8];
    const float* attb   = (const float*)d_in[9];
    const float* vvec   = (const float*)d_in[10];
    float* out = (float*)d_out;

    void *pImg16, *pText16, *pWbig, *pWtext, *pBias2048, *pImgpk, *pMxtext;
    cudaGetSymbolAddress(&pImg16,   g_img16);
    cudaGetSymbolAddress(&pText16,  g_text16);
    cudaGetSymbolAddress(&pWbig,    g_Wbig);
    cudaGetSymbolAddress(&pWtext,   g_Wtext);
    cudaGetSymbolAddress(&pBias2048,g_bias2048);
    cudaGetSymbolAddress(&pImgpk,   g_imgpk);
    cudaGetSymbolAddress(&pMxtext,  g_mxtext);

    constexpr int GEMM_SMEM = 2 * (128 * (32 + 8) * 2 + 32 * (256 + 8) * 2);  // 54272
    cudaFuncSetAttribute(gemm_pipe<128, 256, 32, 64, 64, true>,
                         cudaFuncAttributeMaxDynamicSharedMemorySize, GEMM_SMEM);
    cudaFuncSetAttribute(gemm_pipe<128, 256, 32, 64, 64, false>,
                         cudaFuncAttributeMaxDynamicSharedMemorySize, GEMM_SMEM);

    // ---- exactly 5 setup launches, so launch #5 is the big GEMM (ncu -s 5) --
    size_t n_img8 = (size_t)B_ * L_ * DI_ / 8;
    cvt_f32_f16_v8<<<(unsigned)((n_img8 + 255) / 256), 256>>>(img, (__half*)pImg16, n_img8);   // 0
    size_t n_txt8 = (size_t)B_ * T_ * DT_ / 8;
    cvt_f32_f16_v8<<<(unsigned)((n_txt8 + 255) / 256), 256>>>(text, (__half*)pText16, n_txt8); // 1
    copy_weights<<<dim3(512, 3), 256>>>(wimg, kernel);                                         // 2
    build_Wh_v8<<<(U_ * HN_ / 8) / 256, 256>>>(attk, reck);                                    // 3
    build_misc<<<(B_ * U_ + 255) / 256, 256>>>(bimg, attb, rbias);                             // 4

    // one-time GEMMs
    // fused: [imgproj | img_k] = img16 @ Wbig + bias2048 -> fp16 [16384, 2048]
    gemm_pipe<128, 256, 32, 64, 64, true>
        <<<dim3(16384 / 128, NF_ / 256), 256, GEMM_SMEM>>>(                                    // 5
        (const __half*)pImg16, (const __half*)pWbig, (const float*)pBias2048,
        nullptr, (__half*)pImgpk, 16384, NF_, DI_);
    // mx_text = text16 @ Wtext + ibias -> fp32 [8192, 1536]
    gemm_pipe<128, 256, 32, 64, 64, false>
        <<<dim3(8192 / 128, U3_ / 256), 256, GEMM_SMEM>>>(                                     // 6
        (const __half*)pText16, (const __half*)pWtext, ibias,
        (float*)pMxtext, nullptr, 8192, U3_, DT_);

    // fully fused sequential GRU loop (persistent kernel, software grid sync)
    persist_loop<<<B_, 256>>>(vvec, out);                                                      // 7
}

// round 11
// speedup vs baseline: 1.0479x; 1.0479x over previous
#include <cuda_runtime.h>
#include <cuda_fp16.h>
#include <mma.h>
#include <cstddef>
#include <cstdint>

using namespace nvcuda;

// Problem dims (fixed by the dataset)
#define B_   256
#define L_   64
#define DI_  2048
#define T_   32
#define DT_  512
#define U_   512
#define A_   512
#define U3_  1536
#define HN_  2048   // combined h-GEMM output: hproj(512) | mi(1536)
#define NF_  2048   // fused img GEMM width: imgproj(512) | imgk(1536)

// ---------------- device scratch (static, allocation-free) ----------------
__device__ __half g_img16  [(size_t)B_*L_*DI_];     // fp16 img [M,K] row-major
__device__ __half g_text16 [(size_t)B_*T_*DT_];
__device__ __half g_Wbig   [(size_t)DI_*NF_];       // [wimg | wctx]  [K=2048, N=2048] row-major
__device__ __half g_Wtext  [(size_t)DT_*U3_];       // kernel[:512]   [K=512,  N=1536] row-major
__device__ float  g_bias2048[NF_];                  // [att_img_bias | 0]
__device__ __half g_Wh16   [U_*HN_];                // [att_hidden | recurrent] row-major
__device__ float  g_hbias  [HN_];
__device__ __half g_imgpk  [(size_t)B_*L_*NF_];     // fused: imgproj | imgk
__device__ float  g_mxtext [(size_t)B_*T_*U3_];     // text @ kernel[:512] + bias
__device__ float  g_hmi    [B_*HN_];                // per-step h-GEMM out
__device__ float  g_h      [B_*U_];
__device__ __half g_h16    [B_*U_];
__device__ unsigned g_barcnt;

// ---------------- small helpers ----------------
__device__ __forceinline__ float tanh_fast(float x) {
    float y; asm("tanh.approx.f32 %0, %1;" : "=f"(y) : "f"(x)); return y;
}
__device__ __forceinline__ void cp_async16(void* sm, const void* gm) {
    unsigned s = (unsigned)__cvta_generic_to_shared(sm);
    asm volatile("cp.async.cg.shared.global [%0], [%1], 16;\n" :: "r"(s), "l"(gm));
}
__device__ __forceinline__ void cp_commit() { asm volatile("cp.async.commit_group;\n"); }
__device__ __forceinline__ void cp_wait0()  { asm volatile("cp.async.wait_group 0;\n"); }

// software grid barrier (all CTAs resident by construction)
__device__ __forceinline__ void grid_sync(unsigned target) {
    __syncthreads();
    if (threadIdx.x == 0) {
        asm volatile("fence.acq_rel.gpu;" ::: "memory");
        asm volatile("red.relaxed.gpu.add.u32 [%0], 1;" :: "l"(&g_barcnt) : "memory");
        unsigned v;
        do {
            asm volatile("ld.acquire.gpu.u32 %0, [%1];" : "=r"(v) : "l"(&g_barcnt) : "memory");
            if (v < target) __nanosleep(32);
        } while (v < target);
    }
    __syncthreads();
}

// ---------------- setup kernels ----------------
// vectorized fp32 -> fp16
__global__ void cvt_f32_f16_v8(const float* __restrict__ s, __half* __restrict__ d, size_t n8) {
    size_t i = (size_t)blockIdx.x * blockDim.x + threadIdx.x;
    if (i >= n8) return;
    const float4* s4 = reinterpret_cast<const float4*>(s) + i * 2;
    float4 a = s4[0], b = s4[1];
    __half2 h[4];
    h[0] = __floats2half2_rn(a.x, a.y);
    h[1] = __floats2half2_rn(a.z, a.w);
    h[2] = __floats2half2_rn(b.x, b.y);
    h[3] = __floats2half2_rn(b.z, b.w);
    reinterpret_cast<uint4*>(d)[i] = *reinterpret_cast<uint4*>(h);
}

// copy+cvt the three K-major weight slabs (sources already [K,N] row-major)
__global__ void copy_weights(const float* __restrict__ wimg, const float* __restrict__ kernel) {
    const int job = blockIdx.y;
    const float* src; __half* dst;
    int rows, cols, dst_ld, n0out;
    if (job == 0)      { src = wimg;                       rows = DI_; cols = 512;  dst = g_Wbig;  dst_ld = NF_; n0out = 0;   }
    else if (job == 1) { src = kernel + (size_t)DT_ * U3_; rows = DI_; cols = U3_;  dst = g_Wbig;  dst_ld = NF_; n0out = 512; }
    else               { src = kernel;                     rows = DT_; cols = U3_;  dst = g_Wtext; dst_ld = U3_; n0out = 0;   }
    const int cols8 = cols / 8;
    const int total = rows * cols8;
    for (int i8 = blockIdx.x * blockDim.x + threadIdx.x; i8 < total;
         i8 += gridDim.x * blockDim.x) {
        int r = i8 / cols8, c = (i8 % cols8) * 8;
        const float* sp = src + (size_t)r * cols + c;
        float4 a = reinterpret_cast<const float4*>(sp)[0];
        float4 b = reinterpret_cast<const float4*>(sp)[1];
        __half2 h[4];
        h[0] = __floats2half2_rn(a.x, a.y);
        h[1] = __floats2half2_rn(a.z, a.w);
        h[2] = __floats2half2_rn(b.x, b.y);
        h[3] = __floats2half2_rn(b.z, b.w);
        *reinterpret_cast<uint4*>(dst + (size_t)r * dst_ld + n0out + c) =
            *reinterpret_cast<uint4*>(h);
    }
}

// Wh = [att_hidden | recurrent] fp16 row-major
__global__ void build_Wh_v8(const float* __restrict__ attk, const float* __restrict__ reck) {
    int i8 = blockIdx.x * blockDim.x + threadIdx.x;     // U_*HN_/8
    if (i8 >= U_ * HN_ / 8) return;
    int k = i8 >> 8, c = (i8 & 255) * 8;
    const float* src = (c < 512) ? (attk + (size_t)k * 512 + c)
                                 : (reck + (size_t)k * U3_ + (c - 512));
    float4 a = reinterpret_cast<const float4*>(src)[0];
    float4 b = reinterpret_cast<const float4*>(src)[1];
    __half2 h[4];
    h[0] = __floats2half2_rn(a.x, a.y);
    h[1] = __floats2half2_rn(a.z, a.w);
    h[2] = __floats2half2_rn(b.x, b.y);
    h[3] = __floats2half2_rn(b.z, b.w);
    reinterpret_cast<uint4*>(g_Wh16)[i8] = *reinterpret_cast<uint4*>(h);
}

// biases + h init + barrier reset
__global__ void build_misc(const float* __restrict__ bimg,
                           const float* __restrict__ attb, const float* __restrict__ recb) {
    int i = blockIdx.x * blockDim.x + threadIdx.x;
    if (i == 0) g_barcnt = 0;
    if (i < NF_) g_bias2048[i] = (i < 512) ? bimg[i] : 0.f;
    if (i < HN_) g_hbias[i]    = (i < 512) ? attb[i] : recb[i - 512];
    if (i < B_ * U_) { g_h[i] = 0.f; g_h16[i] = __float2half(0.f); }
}

// ---------------- cp.async double-buffered WMMA GEMM -----------------------
// C[M,N] = A[M,K] @ B[K,N] (+bias via accumulator init), out fp32 or fp16.
// 256 threads = 8 warps; R6-proven 128x128x32 geometry, static smem.
// __launch_bounds__(256, 2): cap 128 regs/thread -> 2 CTAs/SM for latency hiding.
template<int BM, int BN, int BK, int WM, int WN, bool OUT_HALF>
__global__ __launch_bounds__(256, 2)
void gemm_pipe(const __half* __restrict__ A, const __half* __restrict__ Bm,
               const float* __restrict__ bias, float* __restrict__ Cf,
               __half* __restrict__ Ch, int M, int N, int K)
{
    constexpr int WARPS_M = BM / WM, WARPS_N = BN / WN;
    static_assert(WARPS_M * WARPS_N == 8, "8 warps");
    constexpr int FM = WM / 16, FN = WN / 16;
    constexpr int ASTR = BK + 8, BSTR = BN + 8;          // half strides (16B-mult rows)
    constexpr int ABYTES = BM * ASTR * 2, BBYTES = BK * BSTR * 2;
    __shared__ __align__(16) char smem[2 * (ABYTES + BBYTES)];

    const int tid = threadIdx.x, lane = tid & 31, wid = tid >> 5;
    const int wm = wid / WARPS_N, wn = wid % WARPS_N;
    const int m0 = blockIdx.x * BM, n0 = blockIdx.y * BN;

    wmma::fragment<wmma::accumulator, 16, 16, 16, float> acc[FM][FN];

    // bias folded into accumulator init via 16-row broadcast tile in smem
    if (bias) {
        float* biasT = reinterpret_cast<float*>(smem);   // [16][BN]
        for (int idx = tid; idx < 16 * BN; idx += 256) biasT[idx] = bias[n0 + (idx % BN)];
        __syncthreads();
        #pragma unroll
        for (int i = 0; i < FM; i++)
            #pragma unroll
            for (int j = 0; j < FN; j++)
                wmma::load_matrix_sync(acc[i][j], biasT + wn * WN + j * 16, BN,
                                       wmma::mem_row_major);
        __syncthreads();
    } else {
        #pragma unroll
        for (int i = 0; i < FM; i++)
            #pragma unroll
            for (int j = 0; j < FN; j++) wmma::fill_fragment(acc[i][j], 0.f);
    }

    auto As = [&](int s) { return reinterpret_cast<__half*>(smem + s * ABYTES); };
    auto Bs = [&](int s) { return reinterpret_cast<__half*>(smem + 2 * ABYTES + s * BBYTES); };

    auto load_tiles = [&](int s, int k0) {
        __half* a = As(s);
        constexpr int AV = BM * BK / 8;
        #pragma unroll
        for (int v = tid; v < AV; v += 256) {
            int r = v / (BK / 8), c = (v % (BK / 8)) * 8;
            cp_async16(a + r * ASTR + c, A + (size_t)(m0 + r) * K + k0 + c);
        }
        __half* b = Bs(s);
        constexpr int BV = BK * BN / 8;
        #pragma unroll
        for (int v = tid; v < BV; v += 256) {
            int r = v / (BN / 8), c = (v % (BN / 8)) * 8;
            cp_async16(b + r * BSTR + c, Bm + (size_t)(k0 + r) * N + n0 + c);
        }
    };

    const int KT = K / BK;
    load_tiles(0, 0);
    cp_commit();

    for (int kt = 0; kt < KT; kt++) {
        const int cur = kt & 1;
        cp_wait0();
        __syncthreads();
        if (kt + 1 < KT) { load_tiles(cur ^ 1, (kt + 1) * BK); cp_commit(); }

        const __half* a = As(cur);
        const __half* b = Bs(cur);
        #pragma unroll
        for (int kk = 0; kk < BK / 16; kk++) {
            wmma::fragment<wmma::matrix_a, 16, 16, 16, __half, wmma::row_major> af[FM];
            wmma::fragment<wmma::matrix_b, 16, 16, 16, __half, wmma::row_major> bf[FN];
            #pragma unroll
            for (int i = 0; i < FM; i++)
                wmma::load_matrix_sync(af[i], a + (wm * WM + i * 16) * ASTR + kk * 16, ASTR);
            #pragma unroll
            for (int j = 0; j < FN; j++)
                wmma::load_matrix_sync(bf[j], b + (kk * 16) * BSTR + wn * WN + j * 16, BSTR);
            #pragma unroll
            for (int i = 0; i < FM; i++)
                #pragma unroll
                for (int j = 0; j < FN; j++)
                    wmma::mma_sync(acc[i][j], af[i], bf[j], acc[i][j]);
        }
        __syncthreads();
    }

    if (OUT_HALF) {
        // per-warp smem staging (aliases pipeline buffers) -> fp16 uint4 stores
        float* stageW = reinterpret_cast<float*>(smem) + wid * 16 * 20;   // [16][20]
        const int r = lane >> 1, c0 = (lane & 1) * 8;
        #pragma unroll
        for (int i = 0; i < FM; i++)
            #pragma unroll
            for (int j = 0; j < FN; j++) {
                wmma::store_matrix_sync(stageW, acc[i][j], 20, wmma::mem_row_major);
                __syncwarp();
                const float* sp = stageW + r * 20 + c0;
                __half2 h[4];
                h[0] = __floats2half2_rn(sp[0], sp[1]);
                h[1] = __floats2half2_rn(sp[2], sp[3]);
                h[2] = __floats2half2_rn(sp[4], sp[5]);
                h[3] = __floats2half2_rn(sp[6], sp[7]);
                size_t g = (size_t)(m0 + wm * WM + i * 16 + r) * N
                         + n0 + wn * WN + j * 16 + c0;
                *reinterpret_cast<uint4*>(Ch + g) = *reinterpret_cast<uint4*>(h);
                __syncwarp();
            }
    } else {
        #pragma unroll
        for (int i = 0; i < FM; i++)
            #pragma unroll
            for (int j = 0; j < FN; j++)
                wmma::store_matrix_sync(
                    Cf + (size_t)(m0 + wm * WM + i * 16) * N + n0 + wn * WN + j * 16,
                    acc[i][j], N, wmma::mem_row_major);
    }
}

// ---------------- persistent fused step loop (R6-proven, unchanged) -------
#define G_ASTR (64 + 8)
#define G_BSTR (32 + 8)
#define G_ABYTES (64 * G_ASTR * 2)
#define G_BBYTES (64 * G_BSTR * 2)

struct PersistSmem {
    float sv[A_];            // persistent: att_v kernel
    float sbias[16 * 32];    // persistent: bias broadcast tile for G
    union {
        char  gbuf[2 * (G_ABYTES + G_BBYTES)];
        struct { float hp[A_]; float sc[L_]; float att[L_]; } s;
    } u;
};

__global__ __launch_bounds__(256, 2)
void persist_loop(const float* __restrict__ v, float* __restrict__ out)
{
    __shared__ PersistSmem sm;
    const int tid = threadIdx.x, lane = tid & 31, wid = tid >> 5;
    const int cta = blockIdx.x;

    const int gm0 = (cta >> 6) * 64;
    const int gn0 = (cta & 63) * 32;
    const int wm = wid >> 1, wn = wid & 1;

    for (int j = tid; j < A_; j += 256) sm.sv[j] = v[j];
    for (int j = tid; j < 16 * 32; j += 256) sm.sbias[j] = g_hbias[gn0 + (j & 31)];
    __syncthreads();

    unsigned nbar = 0;

    for (int t = 0; t < T_; t++) {
        // Phase G: hmi = h16 @ Wh16 + hbias
        {
            wmma::fragment<wmma::accumulator, 16, 16, 16, float> acc;
            wmma::load_matrix_sync(acc, sm.sbias + wn * 16, 32, wmma::mem_row_major);

            auto As = [&](int s) { return reinterpret_cast<__half*>(sm.u.gbuf + s * (G_ABYTES + G_BBYTES)); };
            auto Bs = [&](int s) { return reinterpret_cast<__half*>(sm.u.gbuf + s * (G_ABYTES + G_BBYTES) + G_ABYTES); };
            auto load_tiles = [&](int s, int k0) {
                __half* a = As(s);
                #pragma unroll
                for (int vv = tid; vv < 64 * 64 / 8; vv += 256) {
                    int r = vv >> 3, c = (vv & 7) * 8;
                    cp_async16(a + r * G_ASTR + c, g_h16 + (size_t)(gm0 + r) * U_ + k0 + c);
                }
                __half* b = Bs(s);
                #pragma unroll
                for (int vv = tid; vv < 64 * 32 / 8; vv += 256) {
                    int r = vv >> 2, c = (vv & 3) * 8;
                    cp_async16(b + r * G_BSTR + c, g_Wh16 + (size_t)(k0 + r) * HN_ + gn0 + c);
                }
            };

            load_tiles(0, 0);
            cp_commit();
            #pragma unroll
            for (int kt = 0; kt < 8; kt++) {
                cp_wait0();
                __syncthreads();
                if (kt + 1 < 8) { load_tiles((kt + 1) & 1, (kt + 1) * 64); cp_commit(); }
                const __half* a = As(kt & 1);
                const __half* b = Bs(kt & 1);
                #pragma unroll
                for (int kk = 0; kk < 4; kk++) {
                    wmma::fragment<wmma::matrix_a, 16, 16, 16, __half, wmma::row_major> af;
                    wmma::fragment<wmma::matrix_b, 16, 16, 16, __half, wmma::row_major> bf;
                    wmma::load_matrix_sync(af, a + (wm * 16) * G_ASTR + kk * 16, G_ASTR);
                    wmma::load_matrix_sync(bf, b + (kk * 16) * G_BSTR + wn * 16, G_BSTR);
                    wmma::mma_sync(acc, af, bf, acc);
                }
                __syncthreads();
            }
            wmma::store_matrix_sync(g_hmi + (size_t)(gm0 + wm * 16) * HN_ + gn0 + wn * 16,
                                    acc, HN_, wmma::mem_row_major);
        }
        grid_sync(++nbar * 256u);

        // Phase S: attention + softmax + ctx + gates
        {
            const int b = cta;
            const float* hmi = g_hmi + b * HN_;
            for (int j = tid; j < A_; j += 256) sm.u.s.hp[j] = __ldcg(&hmi[j]);
            __syncthreads();

            const __half2* base2 = reinterpret_cast<const __half2*>(g_imgpk + (size_t)b * L_ * NF_);
            for (int l = wid; l < L_; l += 8) {
                const __half2* ip = base2 + (size_t)l * (NF_ / 2);
                float s = 0.f;
                #pragma unroll 4
                for (int a2 = lane; a2 < A_ / 2; a2 += 32) {
                    float2 f = __half22float2(ip[a2]);
                    int a = a2 * 2;
                    s += tanh_fast(f.x + sm.u.s.hp[a])     * sm.sv[a];
                    s += tanh_fast(f.y + sm.u.s.hp[a + 1]) * sm.sv[a + 1];
                }
                #pragma unroll
                for (int o = 16; o; o >>= 1) s += __shfl_xor_sync(0xffffffffu, s, o);
                if (!lane) sm.u.s.sc[l] = s;
            }
            __syncthreads();

            if (tid < 32) {
                float v1 = sm.u.s.sc[tid], v2 = sm.u.s.sc[tid + 32];
                float m = fmaxf(v1, v2);
                #pragma unroll
                for (int o = 16; o; o >>= 1) m = fmaxf(m, __shfl_xor_sync(0xffffffffu, m, o));
                float e1 = expf(v1 - m), e2 = expf(v2 - m);
                float ssum = e1 + e2;
                #pragma unroll
                for (int o = 16; o; o >>= 1) ssum += __shfl_xor_sync(0xffffffffu, ssum, o);
                float inv = 1.f / ssum;
                sm.u.s.att[tid] = e1 * inv;
                sm.u.s.att[tid + 32] = e2 * inv;
            }
            __syncthreads();

            float acc6[6] = {0.f, 0.f, 0.f, 0.f, 0.f, 0.f};
            for (int l = 0; l < L_; l++) {
                float w = sm.u.s.att[l];
                const __half2* row = base2 + (size_t)l * (NF_ / 2) + 256;
                #pragma unroll
                for (int c = 0; c < 3; c++) {
                    float2 f = __half22float2(row[tid + c * 256]);
                    acc6[2 * c]     += w * f.x;
                    acc6[2 * c + 1] += w * f.y;
                }
            }

            const float* mxt = g_mxtext + ((size_t)b * T_ + t) * U3_;
            #pragma unroll
            for (int p = 0; p < 2; p++) {
                int u = tid * 2 + p;
                float xz = mxt[u]        + acc6[p];
                float xr = mxt[512 + u]  + acc6[2 + p];
                float xh = mxt[1024 + u] + acc6[4 + p];
                float rz = __ldcg(&hmi[512 + u]);
                float rr = __ldcg(&hmi[1024 + u]);
                float rh = __ldcg(&hmi[1536 + u]);
                float z  = 1.f / (1.f + expf(-(xz + rz)));
                float r  = 1.f / (1.f + expf(-(xr + rr)));
                float hh = tanhf(xh + r * rh);
                float ho = g_h[b * U_ + u];
                float hn = z * ho + (1.f - z) * hh;
                out[((size_t)b * T_ + t) * U_ + u] = hn;
                g_h[b * U_ + u]   = hn;
                g_h16[b * U_ + u] = __float2half(hn);
            }
        }
        if (t + 1 < T_) grid_sync(++nbar * 256u);
    }
}

// ---------------- host launcher ----------------
extern "C" void kernel_launch(void* const* d_in, const int* in_sizes, int n_in,
                              void* d_out, int out_size)
{
    const float* img    = (const float*)d_in[0];
    const float* text   = (const float*)d_in[1];
    const float* kernel = (const float*)d_in[2];
    const float* ibias  = (const float*)d_in[3];
    const float* reck   = (const float*)d_in[4];
    const float* rbias  = (const float*)d_in[5];
    const float* wimg   = (const float*)d_in[6];
    const float* bimg   = (const float*)d_in[7];
    const float* attk   = (const float*)d_in[8];
    const float* attb   = (const float*)d_in[9];
    const float* vvec   = (const float*)d_in[10];
    float* out = (float*)d_out;

    void *pImg16, *pText16, *pWbig, *pWtext, *pBias2048, *pImgpk, *pMxtext;
    cudaGetSymbolAddress(&pImg16,   g_img16);
    cudaGetSymbolAddress(&pText16,  g_text16);
    cudaGetSymbolAddress(&pWbig,    g_Wbig);
    cudaGetSymbolAddress(&pWtext,   g_Wtext);
    cudaGetSymbolAddress(&pBias2048,g_bias2048);
    cudaGetSymbolAddress(&pImgpk,   g_imgpk);
    cudaGetSymbolAddress(&pMxtext,  g_mxtext);

    // ---- setup launches ----
    size_t n_img8 = (size_t)B_ * L_ * DI_ / 8;
    cvt_f32_f16_v8<<<(unsigned)((n_img8 + 255) / 256), 256>>>(img, (__half*)pImg16, n_img8);   // 0
    size_t n_txt8 = (size_t)B_ * T_ * DT_ / 8;
    cvt_f32_f16_v8<<<(unsigned)((n_txt8 + 255) / 256), 256>>>(text, (__half*)pText16, n_txt8); // 1
    copy_weights<<<dim3(512, 3), 256>>>(wimg, kernel);                                         // 2
    build_Wh_v8<<<(U_ * HN_ / 8) / 256, 256>>>(attk, reck);                                    // 3
    build_misc<<<(B_ * U_ + 255) / 256, 256>>>(bimg, attb, rbias);                             // 4

    // one-time GEMMs (R6 geometry + forced 2 CTAs/SM)
    // fused: [imgproj | img_k] = img16 @ Wbig + bias2048 -> fp16 [16384, 2048]
    gemm_pipe<128, 128, 32, 64, 32, true><<<dim3(16384 / 128, NF_ / 128), 256>>>(              // 5
        (const __half*)pImg16, (const __half*)pWbig, (const float*)pBias2048,
        nullptr, (__half*)pImgpk, 16384, NF_, DI_);
    // mx_text = text16 @ Wtext + ibias -> fp32 [8192, 1536]
    gemm_pipe<128, 128, 32, 64, 32, false><<<dim3(8192 / 128, U3_ / 128), 256>>>(              // 6
        (const __half*)pText16, (const __half*)pWtext, ibias,
        (float*)pMxtext, nullptr, 8192, U3_, DT_);

    // fully fused sequential GRU loop (persistent kernel, software grid sync)
    persist_loop<<<B_, 256>>>(vvec, out);                                                      // 7
}